// round 6
// baseline (speedup 1.0000x reference)
#include <cuda_runtime.h>
#include <cstdint>
#include <cstddef>

#define SEQ     4096
#define DMODEL  2048
#define DH      128
#define CHUNK   512
#define MAXC    8

// Scratch (allocation-free rule: __device__ globals)
__device__ float g_Q[SEQ * DH];
__device__ float g_K[SEQ * DH];
__device__ float g_V[SEQ * DH];
// W pre-converted to tf32, fragment-pair order: [3][256 kb][128 n][4 t4][2]
__device__ float g_Wf[3 * 256 * 128 * 8];
// split-KV partials
__device__ float g_Opart[64 * MAXC * 64 * DH];
__device__ float g_mpart[64 * MAXC * 64];
__device__ float g_lpart[64 * MAXC * 64];

__device__ __forceinline__ uint32_t f2tf(float x) {
    uint32_t r;
    asm("cvt.rna.tf32.f32 %0, %1;" : "=r"(r) : "f"(x));
    return r;
}
__device__ __forceinline__ float ex2(float x) {
    float y;
    asm("ex2.approx.ftz.f32 %0, %1;" : "=f"(y) : "f"(x));
    return y;
}
__device__ __forceinline__ void mma_tf32(float d[4], const uint32_t a[4],
                                         uint32_t b0, uint32_t b1) {
    asm volatile(
        "mma.sync.aligned.m16n8k8.row.col.f32.tf32.tf32.f32 "
        "{%0,%1,%2,%3},{%4,%5,%6,%7},{%8,%9},{%0,%1,%2,%3};\n"
        : "+f"(d[0]), "+f"(d[1]), "+f"(d[2]), "+f"(d[3])
        : "r"(a[0]), "r"(a[1]), "r"(a[2]), "r"(a[3]), "r"(b0), "r"(b1));
}
__device__ __forceinline__ void cpa16(uint32_t dst, const void* src) {
    asm volatile("cp.async.cg.shared.global [%0], [%1], 16;\n" :: "r"(dst), "l"(src));
}
__device__ __forceinline__ void cp_commit() {
    asm volatile("cp.async.commit_group;\n" ::);
}
template <int N>
__device__ __forceinline__ void cp_wait() {
    asm volatile("cp.async.wait_group %0;\n" :: "n"(N));
}
__device__ __forceinline__ uint32_t s2u(const void* p) {
    return (uint32_t)__cvta_generic_to_shared(p);
}

// ---------------------------------------------------------------------------
// prep_w: round W to tf32 and reorder into MMA b-fragment pairs:
// g_Wf[mat][kb][n][t4][2] = { W[n][8kb+t4], W[n][8kb+t4+4] }
// ---------------------------------------------------------------------------
__global__ __launch_bounds__(256)
void prep_w(const float* __restrict__ wq, const float* __restrict__ wk,
            const float* __restrict__ wv) {
    int id = blockIdx.x * 256 + threadIdx.x;       // 0 .. 393215
    int mat = id >> 17;
    int rem = id & 131071;
    int kb = rem >> 9;
    int rem2 = rem & 511;
    int n = rem2 >> 2;
    int t4 = rem2 & 3;
    const float* W = (mat == 0) ? wq : (mat == 1) ? wk : wv;
    float a = W[(size_t)n * DMODEL + kb * 8 + t4];
    float b = W[(size_t)n * DMODEL + kb * 8 + t4 + 4];
    float2 o;
    o.x = __uint_as_float(f2tf(a));
    o.y = __uint_as_float(f2tf(b));
    *(float2*)&g_Wf[(((size_t)mat * 256 + kb) * 128 + n) * 8 + t4 * 2] = o;
}

// ---------------------------------------------------------------------------
// Projection v3: 64(M) x 128(N) tile, KSTEP=16, depth-4 cp.async pipeline.
// Dynamic smem: Xs[4][64][28] raw fp32, Wf[4][2][128][12] pre-tf32 pairs.
// One __syncthreads per iteration; wait_group(2) = 3-iteration latency cover.
// ---------------------------------------------------------------------------
#define PJ_DEPTH 4
#define XS_STR   28   // bank = (28g + t4)%32 distinct; 112B row, 16B-aligned
#define WF_STR   12   // 48B row, 16B-aligned for cp.async
#define PJ_SMEM  (PJ_DEPTH*64*XS_STR*4 + PJ_DEPTH*2*128*WF_STR*4)  // 77824

__global__ __launch_bounds__(256, 2)
void proj_kernel(const float* __restrict__ xq, const float* __restrict__ xk,
                 const float* __restrict__ xv,
                 const float* __restrict__ bq, const float* __restrict__ bk,
                 const float* __restrict__ bv) {
    extern __shared__ float sm[];
    float* Xs = sm;                              // [4][64][28]
    float* Wf = sm + PJ_DEPTH * 64 * XS_STR;     // [4][2][128][12]

    const float* X; const float* bias; float* out; int mat;
    if (blockIdx.y == 0)      { X = xq; bias = bq; out = g_Q; mat = 0; }
    else if (blockIdx.y == 1) { X = xk; bias = bk; out = g_K; mat = 1; }
    else                      { X = xv; bias = bv; out = g_V; mat = 2; }

    const int tid  = threadIdx.x;
    const int warp = tid >> 5, lane = tid & 31;
    const int g    = lane >> 2, t4 = lane & 3;
    const int wm   = warp >> 1;   // 0..3 : 16 M-rows
    const int wn   = warp & 1;    // 0..1 : 64 N-cols
    const int m0   = blockIdx.x * 64;

    const float* gwf = g_Wf + (size_t)mat * 256 * 128 * 8;

    // cp.async issue of stage number sidx (k0 = sidx*16), slot sidx%4
    auto issue = [&](int sidx) {
        const int s  = sidx & (PJ_DEPTH - 1);
        const int k0 = (sidx & 127) * 16;
        // X: 64 rows x 16 floats = 256 chunks of 16B -> 1 per thread
        {
            int r = tid >> 2, c4 = (tid & 3) * 4;
            cpa16(s2u(&Xs[(s * 64 + r) * XS_STR + c4]),
                  X + (size_t)(m0 + r) * DMODEL + k0 + c4);
        }
        // W frags: 2 kb x 128 n x 8 floats = 512 chunks -> 2 per thread
#pragma unroll
        for (int t = 0; t < 2; ++t) {
            int id = tid + t * 256;
            int kb = id >> 8;
            int rem = id & 255;
            int n = rem >> 1, half = rem & 1;
            cpa16(s2u(&Wf[((s * 2 + kb) * 128 + n) * WF_STR + half * 4]),
                  gwf + (((size_t)(k0 >> 3) + kb) * 128 + n) * 8 + half * 4);
        }
        cp_commit();
    };

    float acc[8][4] = {};

    issue(0); issue(1); issue(2);

    const int NK = DMODEL / 16;   // 128
    for (int i = 0; i < NK; ++i) {
        cp_wait<2>();
        __syncthreads();
        issue(i + 3);             // wraps past NK: overwrites retired slots only

        const int s = i & (PJ_DEPTH - 1);
#pragma unroll
        for (int kk = 0; kk < 2; ++kk) {
            uint32_t a[4];
            {
                int r = wm * 16 + g;
                int c = kk * 8 + t4;
                a[0] = f2tf(Xs[(s * 64 + r) * XS_STR + c]);
                a[1] = f2tf(Xs[(s * 64 + r + 8) * XS_STR + c]);
                a[2] = f2tf(Xs[(s * 64 + r) * XS_STR + c + 4]);
                a[3] = f2tf(Xs[(s * 64 + r + 8) * XS_STR + c + 4]);
            }
#pragma unroll
            for (int nt = 0; nt < 8; ++nt) {
                int n = wn * 64 + nt * 8 + g;
                float2 w2 = *(float2*)&Wf[((s * 2 + kk) * 128 + n) * WF_STR + t4 * 2];
                mma_tf32(acc[nt], a, __float_as_uint(w2.x), __float_as_uint(w2.y));
            }
        }
    }

#pragma unroll
    for (int nt = 0; nt < 8; ++nt) {
        int r = m0 + wm * 16 + g;
        int c = wn * 64 + nt * 8 + t4 * 2;
        float b0 = bias[c], b1 = bias[c + 1];
        out[(size_t)r * DH + c]           = __uint_as_float(f2tf(acc[nt][0] + b0));
        out[(size_t)r * DH + c + 1]       = __uint_as_float(f2tf(acc[nt][1] + b1));
        out[(size_t)(r + 8) * DH + c]     = __uint_as_float(f2tf(acc[nt][2] + b0));
        out[(size_t)(r + 8) * DH + c + 1] = __uint_as_float(f2tf(acc[nt][3] + b1));
    }
}

// ---------------------------------------------------------------------------
// Split-KV causal flash attention, depth-2 cp.async K/V pipeline.
// Dynamic smem: Ks[2][32][132] + Vs[2][32][136] + Ps[4][16][36] = 77824 B.
// ---------------------------------------------------------------------------
#define BM 64
#define BN 32
#define KSTR 132
#define VSTR 136
#define AT_SMEM (2*BN*KSTR*4 + 2*BN*VSTR*4 + 4*16*36*4)   // 77824

__global__ __launch_bounds__(128, 2)
void attn_kernel(float* __restrict__ out) {
    const int qt = blockIdx.x;
    const int ch = blockIdx.y;
    const int nc = (qt >> 3) + 1;
    if (ch >= nc) return;

    extern __shared__ float sm[];
    float* Ks = sm;                       // [2][32][132]
    float* Vs = sm + 2 * BN * KSTR;       // [2][32][136]
    float* Ps = sm + 2 * BN * KSTR + 2 * BN * VSTR;  // [4][16][36]

    const int tid  = threadIdx.x;
    const int warp = tid >> 5, lane = tid & 31;
    const int g    = lane >> 2, t4 = lane & 3;
    const int qm0  = qt * BM;
    const int row_base = qm0 + warp * 16;
    const float NEG_INF = __int_as_float(0xff800000u);
    const float SC = 0.02209708691207961f * 1.4426950408889634f;

    const int kstart = ch * CHUNK;
    const int kend   = min(kstart + CHUNK, qm0 + BM);
    const int ntiles = (kend - kstart) / BN;

    auto issue = [&](int j) {   // stage j -> slot j&1, keys [kstart+j*BN, +BN)
        const int s = j & 1;
        const int n0 = kstart + j * BN;
#pragma unroll
        for (int t = 0; t < 8; ++t) {
            int i = tid + t * 128;
            int r = i >> 5, c4 = (i & 31) * 4;
            cpa16(s2u(&Ks[(s * BN + r) * KSTR + c4]),
                  g_K + (size_t)(n0 + r) * DH + c4);
            cpa16(s2u(&Vs[(s * BN + r) * VSTR + c4]),
                  g_V + (size_t)(n0 + r) * DH + c4);
        }
        cp_commit();
    };

    // Q fragments (pre-rounded tf32 bits from proj)
    uint32_t qf[16][4];
#pragma unroll
    for (int kt = 0; kt < 16; ++kt) {
        const float* qp = g_Q + (size_t)(row_base + g) * DH + kt * 8 + t4;
        qf[kt][0] = __float_as_uint(qp[0]);
        qf[kt][1] = __float_as_uint(qp[8 * DH]);
        qf[kt][2] = __float_as_uint(qp[4]);
        qf[kt][3] = __float_as_uint(qp[8 * DH + 4]);
    }

    float acc[16][4] = {};
    float m0r = NEG_INF, m1r = NEG_INF;
    float l0 = 0.f, l1 = 0.f;

    issue(0);

    for (int j = 0; j < ntiles; ++j) {
        cp_wait<0>();
        __syncthreads();                 // stage j visible to all; slot j+1 free
        if (j + 1 < ntiles) issue(j + 1);

        const int s = j & 1;
        const int n0 = kstart + j * BN;
        const float* K0 = &Ks[(s * BN) * KSTR];
        const float* V0 = &Vs[(s * BN) * VSTR];

        // S = Q . K^T
        float sreg[4][4] = {};
#pragma unroll
        for (int kt = 0; kt < 16; ++kt) {
#pragma unroll
            for (int nt = 0; nt < 4; ++nt) {
                int n = nt * 8 + g;
                int c = kt * 8 + t4;
                uint32_t b0 = __float_as_uint(K0[n * KSTR + c]);
                uint32_t b1 = __float_as_uint(K0[n * KSTR + c + 4]);
                mma_tf32(sreg[nt], qf[kt], b0, b1);
            }
        }

        // exp2-domain scale + causal mask
        const int r0g = row_base + g, r1g = r0g + 8;
        const bool domask = (n0 + BN - 1 > row_base);
#pragma unroll
        for (int nt = 0; nt < 4; ++nt) {
            int c0 = n0 + nt * 8 + t4 * 2;
#pragma unroll
            for (int e = 0; e < 4; ++e) sreg[nt][e] *= SC;
            if (domask) {
                if (c0 > r0g)     sreg[nt][0] = NEG_INF;
                if (c0 + 1 > r0g) sreg[nt][1] = NEG_INF;
                if (c0 > r1g)     sreg[nt][2] = NEG_INF;
                if (c0 + 1 > r1g) sreg[nt][3] = NEG_INF;
            }
        }

        // online softmax
        float mx0 = fmaxf(fmaxf(sreg[0][0], sreg[0][1]), fmaxf(sreg[1][0], sreg[1][1]));
        mx0 = fmaxf(mx0, fmaxf(fmaxf(sreg[2][0], sreg[2][1]), fmaxf(sreg[3][0], sreg[3][1])));
        float mx1 = fmaxf(fmaxf(sreg[0][2], sreg[0][3]), fmaxf(sreg[1][2], sreg[1][3]));
        mx1 = fmaxf(mx1, fmaxf(fmaxf(sreg[2][2], sreg[2][3]), fmaxf(sreg[3][2], sreg[3][3])));
        mx0 = fmaxf(mx0, __shfl_xor_sync(0xffffffffu, mx0, 1));
        mx0 = fmaxf(mx0, __shfl_xor_sync(0xffffffffu, mx0, 2));
        mx1 = fmaxf(mx1, __shfl_xor_sync(0xffffffffu, mx1, 1));
        mx1 = fmaxf(mx1, __shfl_xor_sync(0xffffffffu, mx1, 2));

        float mn0 = fmaxf(m0r, mx0), mn1 = fmaxf(m1r, mx1);
        float mu0 = fmaxf(mn0, -1e30f), mu1 = fmaxf(mn1, -1e30f);
        float al0 = ex2(m0r - mu0), al1 = ex2(m1r - mu1);
        m0r = mn0; m1r = mn1;

        float* Pw = &Ps[warp * 16 * 36];
        float rs0 = 0.f, rs1 = 0.f;
#pragma unroll
        for (int nt = 0; nt < 4; ++nt) {
            float p00 = ex2(sreg[nt][0] - mu0), p01 = ex2(sreg[nt][1] - mu0);
            float p10 = ex2(sreg[nt][2] - mu1), p11 = ex2(sreg[nt][3] - mu1);
            rs0 += p00 + p01; rs1 += p10 + p11;
            Pw[g * 36 + nt * 8 + t4 * 2]           = __uint_as_float(f2tf(p00));
            Pw[g * 36 + nt * 8 + t4 * 2 + 1]       = __uint_as_float(f2tf(p01));
            Pw[(g + 8) * 36 + nt * 8 + t4 * 2]     = __uint_as_float(f2tf(p10));
            Pw[(g + 8) * 36 + nt * 8 + t4 * 2 + 1] = __uint_as_float(f2tf(p11));
        }
        rs0 += __shfl_xor_sync(0xffffffffu, rs0, 1);
        rs0 += __shfl_xor_sync(0xffffffffu, rs0, 2);
        rs1 += __shfl_xor_sync(0xffffffffu, rs1, 1);
        rs1 += __shfl_xor_sync(0xffffffffu, rs1, 2);
        l0 = l0 * al0 + rs0;
        l1 = l1 * al1 + rs1;

#pragma unroll
        for (int nt = 0; nt < 16; ++nt) {
            acc[nt][0] *= al0; acc[nt][1] *= al0;
            acc[nt][2] *= al1; acc[nt][3] *= al1;
        }
        __syncwarp();

        // O += P . V
#pragma unroll
        for (int ks = 0; ks < 4; ++ks) {
            uint32_t a[4];
            a[0] = __float_as_uint(Pw[g * 36 + ks * 8 + t4]);
            a[1] = __float_as_uint(Pw[(g + 8) * 36 + ks * 8 + t4]);
            a[2] = __float_as_uint(Pw[g * 36 + ks * 8 + t4 + 4]);
            a[3] = __float_as_uint(Pw[(g + 8) * 36 + ks * 8 + t4 + 4]);
#pragma unroll
            for (int nt = 0; nt < 16; ++nt) {
                int vn = nt * 8 + g;
                int vk = ks * 8 + t4;
                uint32_t b0 = __float_as_uint(V0[vk * VSTR + vn]);
                uint32_t b1 = __float_as_uint(V0[(vk + 4) * VSTR + vn]);
                mma_tf32(acc[nt], a, b0, b1);
            }
        }
        __syncwarp();
    }

    if (nc == 1) {
        const float inv0 = 1.0f / l0, inv1 = 1.0f / l1;
#pragma unroll
        for (int nt = 0; nt < 16; ++nt) {
            int r = row_base + g;
            int c = nt * 8 + t4 * 2;
            out[(size_t)r * DH + c]           = acc[nt][0] * inv0;
            out[(size_t)r * DH + c + 1]       = acc[nt][1] * inv0;
            out[(size_t)(r + 8) * DH + c]     = acc[nt][2] * inv1;
            out[(size_t)(r + 8) * DH + c + 1] = acc[nt][3] * inv1;
        }
    } else {
        const int pslot = qt * MAXC + ch;
        float* Op = g_Opart + (size_t)pslot * 64 * DH;
        const int lr0 = warp * 16 + g, lr1 = lr0 + 8;
#pragma unroll
        for (int nt = 0; nt < 16; ++nt) {
            int c = nt * 8 + t4 * 2;
            Op[(size_t)lr0 * DH + c]     = acc[nt][0];
            Op[(size_t)lr0 * DH + c + 1] = acc[nt][1];
            Op[(size_t)lr1 * DH + c]     = acc[nt][2];
            Op[(size_t)lr1 * DH + c + 1] = acc[nt][3];
        }
        if (t4 == 0) {
            g_mpart[pslot * 64 + lr0] = m0r;
            g_lpart[pslot * 64 + lr0] = l0;
            g_mpart[pslot * 64 + lr1] = m1r;
            g_lpart[pslot * 64 + lr1] = l1;
        }
    }
}

// ---------------------------------------------------------------------------
__global__ __launch_bounds__(128)
void combine_kernel(float* __restrict__ out) {
    const int row = 512 + blockIdx.x;
    const int qt  = row >> 6;
    const int nc  = (qt >> 3) + 1;
    const int lr  = row & 63;
    const int col = threadIdx.x;

    float M = -1e30f;
    for (int c = 0; c < nc; ++c)
        M = fmaxf(M, g_mpart[(qt * MAXC + c) * 64 + lr]);

    float l = 0.f, o = 0.f;
    for (int c = 0; c < nc; ++c) {
        int pslot = qt * MAXC + c;
        float a = ex2(g_mpart[pslot * 64 + lr] - M);
        l += a * g_lpart[pslot * 64 + lr];
        o += a * g_Opart[((size_t)pslot * 64 + lr) * DH + col];
    }
    out[(size_t)row * DH + col] = o / l;
}

// ---------------------------------------------------------------------------

extern "C" void kernel_launch(void* const* d_in, const int* in_sizes, int n_in,
                              void* d_out, int out_size) {
    (void)in_sizes; (void)n_in; (void)out_size;
    const float* xq = (const float*)d_in[0];
    const float* xk = (const float*)d_in[1];
    const float* xv = (const float*)d_in[2];
    const float* wq = (const float*)d_in[3];
    const float* bq = (const float*)d_in[4];
    const float* wk = (const float*)d_in[5];
    const float* bk = (const float*)d_in[6];
    const float* wv = (const float*)d_in[7];
    const float* bv = (const float*)d_in[8];
    float* out = (float*)d_out;

    cudaFuncSetAttribute(proj_kernel, cudaFuncAttributeMaxDynamicSharedMemorySize, PJ_SMEM);
    cudaFuncSetAttribute(attn_kernel, cudaFuncAttributeMaxDynamicSharedMemorySize, AT_SMEM);

    prep_w<<<1536, 256>>>(wq, wk, wv);
    proj_kernel<<<dim3(SEQ / 64, 3), 256, PJ_SMEM>>>(xq, xk, xv, bq, bk, bv);
    attn_kernel<<<dim3(SEQ / BM, MAXC), 128, AT_SMEM>>>(out);
    combine_kernel<<<SEQ - 512, 128>>>(out);
}

// round 8
// speedup vs baseline: 1.0112x; 1.0112x over previous
#include <cuda_runtime.h>
#include <cstdint>
#include <cstddef>

#define SEQ     4096
#define DMODEL  2048
#define DH      128
#define CHUNK   512
#define MAXC    8

// Scratch (allocation-free rule: __device__ globals)
__device__ float g_Q[SEQ * DH];
__device__ float g_K[SEQ * DH];
__device__ float g_V[SEQ * DH];
// W pre-converted to tf32, fragment-pair order: [3][256 kb][128 n][4 t4][2]
__device__ float g_Wf[3 * 256 * 128 * 8];
// split-KV partials
__device__ float g_Opart[64 * MAXC * 64 * DH];
__device__ float g_mpart[64 * MAXC * 64];
__device__ float g_lpart[64 * MAXC * 64];

__device__ __forceinline__ uint32_t f2tf(float x) {
    uint32_t r;
    asm("cvt.rna.tf32.f32 %0, %1;" : "=r"(r) : "f"(x));
    return r;
}
__device__ __forceinline__ float ex2(float x) {
    float y;
    asm("ex2.approx.ftz.f32 %0, %1;" : "=f"(y) : "f"(x));
    return y;
}
__device__ __forceinline__ void mma_tf32(float d[4], const uint32_t a[4],
                                         uint32_t b0, uint32_t b1) {
    asm volatile(
        "mma.sync.aligned.m16n8k8.row.col.f32.tf32.tf32.f32 "
        "{%0,%1,%2,%3},{%4,%5,%6,%7},{%8,%9},{%0,%1,%2,%3};\n"
        : "+f"(d[0]), "+f"(d[1]), "+f"(d[2]), "+f"(d[3])
        : "r"(a[0]), "r"(a[1]), "r"(a[2]), "r"(a[3]), "r"(b0), "r"(b1));
}

// ---------------------------------------------------------------------------
// prep_w: round W to tf32 and reorder into MMA b-fragment pairs:
// g_Wf[mat][kb][n][t4][2] = { W[n][8kb+t4], W[n][8kb+t4+4] }
// ---------------------------------------------------------------------------
__global__ __launch_bounds__(256)
void prep_w(const float* __restrict__ wq, const float* __restrict__ wk,
            const float* __restrict__ wv) {
    int id = blockIdx.x * 256 + threadIdx.x;       // 0 .. 393215
    int mat = id >> 17;
    int rem = id & 131071;
    int kb = rem >> 9;
    int rem2 = rem & 511;
    int n = rem2 >> 2;
    int t4 = rem2 & 3;
    const float* W = (mat == 0) ? wq : (mat == 1) ? wk : wv;
    float a = W[(size_t)n * DMODEL + kb * 8 + t4];
    float b = W[(size_t)n * DMODEL + kb * 8 + t4 + 4];
    float2 o;
    o.x = __uint_as_float(f2tf(a));
    o.y = __uint_as_float(f2tf(b));
    *(float2*)&g_Wf[(((size_t)mat * 256 + kb) * 128 + n) * 8 + t4 * 2] = o;
}

// ---------------------------------------------------------------------------
// Projection (R1 structure restored): 128(M) x 128(N) tile, 256 thr, grid (32,3).
// X staged raw fp32 (cvt at use); W staged as pre-tf32 fragment pairs ->
// one conflict-free LDS.64 per b-fragment (addr = 8g + 2*t4 covers 32 banks).
// Single-buffer smem with register prefetch (proven ~36us at 128x128).
// ---------------------------------------------------------------------------
#define PSTR 36   // Xs: bank = (4g + t4) % 32, conflict-free

__global__ __launch_bounds__(256, 1)
void proj_kernel(const float* __restrict__ xq, const float* __restrict__ xk,
                 const float* __restrict__ xv,
                 const float* __restrict__ bq, const float* __restrict__ bk,
                 const float* __restrict__ bv) {
    __shared__ float Xs[128][PSTR];        // 18 KB
    __shared__ float Wf[4][128][8];        // 16 KB, [kb][n][frag pair]

    const float* X; const float* bias; float* out; int mat;
    if (blockIdx.y == 0)      { X = xq; bias = bq; out = g_Q; mat = 0; }
    else if (blockIdx.y == 1) { X = xk; bias = bk; out = g_K; mat = 1; }
    else                      { X = xv; bias = bv; out = g_V; mat = 2; }

    const int tid  = threadIdx.x;
    const int warp = tid >> 5, lane = tid & 31;
    const int g    = lane >> 2, t4 = lane & 3;
    const int wm   = warp >> 1;   // 0..3 : 32 M-rows each
    const int wn   = warp & 1;    // 0..1 : 64 N-cols each
    const int m0   = blockIdx.x * 128;

    const float* gwf = g_Wf + (size_t)mat * 256 * 128 * 8;

    float acc[2][8][4] = {};

    float4 xr[4], wr[4];
    auto ld = [&](int k0) {
#pragma unroll
        for (int t = 0; t < 4; ++t) {
            int i = tid + t * 256;
            int r = i >> 3, c4 = (i & 7) * 4;
            xr[t] = *(const float4*)(X + (size_t)(m0 + r) * DMODEL + k0 + c4);
        }
        // W fragments for kb = k0/8 .. k0/8+3 : 4*128*8 floats = 1024 float4
#pragma unroll
        for (int t = 0; t < 4; ++t) {
            int i = tid + t * 256;
            int kb = i >> 8;
            int rem = i & 255;
            int n = rem >> 1, half = rem & 1;
            wr[t] = *(const float4*)(gwf + (((size_t)(k0 >> 3) + kb) * 128 + n) * 8 + half * 4);
        }
    };
    auto st = [&]() {
#pragma unroll
        for (int t = 0; t < 4; ++t) {
            int i = tid + t * 256;
            int r = i >> 3, c4 = (i & 7) * 4;
            *(float4*)&Xs[r][c4] = xr[t];
        }
#pragma unroll
        for (int t = 0; t < 4; ++t) {
            int i = tid + t * 256;
            int kb = i >> 8;
            int rem = i & 255;
            int n = rem >> 1, half = rem & 1;
            *(float4*)&Wf[kb][n][half * 4] = wr[t];
        }
    };

    ld(0); st();
    __syncthreads();

    for (int k0 = 0; k0 < DMODEL; k0 += 32) {
        bool more = (k0 + 32 < DMODEL);
        if (more) ld(k0 + 32);   // overlap global fetch with MMA

#pragma unroll
        for (int kk = 0; kk < 4; ++kk) {     // kb within stage, K-step 8
            uint32_t a[2][4];
#pragma unroll
            for (int mt = 0; mt < 2; ++mt) {
                int r = wm * 32 + mt * 16 + g;
                int c = kk * 8 + t4;
                a[mt][0] = f2tf(Xs[r][c]);
                a[mt][1] = f2tf(Xs[r + 8][c]);
                a[mt][2] = f2tf(Xs[r][c + 4]);
                a[mt][3] = f2tf(Xs[r + 8][c + 4]);
            }
#pragma unroll
            for (int nt = 0; nt < 8; ++nt) {
                int n = wn * 64 + nt * 8 + g;
                float2 w2 = *(float2*)&Wf[kk][n][t4 * 2];   // LDS.64, conflict-free
                uint32_t b0 = __float_as_uint(w2.x);
                uint32_t b1 = __float_as_uint(w2.y);
                mma_tf32(acc[0][nt], a[0], b0, b1);
                mma_tf32(acc[1][nt], a[1], b0, b1);
            }
        }
        __syncthreads();
        if (more) { st(); __syncthreads(); }
    }

#pragma unroll
    for (int mt = 0; mt < 2; ++mt) {
#pragma unroll
        for (int nt = 0; nt < 8; ++nt) {
            int r = m0 + wm * 32 + mt * 16 + g;
            int c = wn * 64 + nt * 8 + t4 * 2;
            float b0 = bias[c], b1 = bias[c + 1];
            out[(size_t)r * DH + c]           = __uint_as_float(f2tf(acc[mt][nt][0] + b0));
            out[(size_t)r * DH + c + 1]       = __uint_as_float(f2tf(acc[mt][nt][1] + b1));
            out[(size_t)(r + 8) * DH + c]     = __uint_as_float(f2tf(acc[mt][nt][2] + b0));
            out[(size_t)(r + 8) * DH + c + 1] = __uint_as_float(f2tf(acc[mt][nt][3] + b1));
        }
    }
}

// ---------------------------------------------------------------------------
// Split-KV causal flash attention (exact R3 version, proven in the 145.4 run).
// grid = (64 q-tiles, 8 chunks), 128 thr.
// ---------------------------------------------------------------------------
#define BM 64
#define BN 32
#define KSTR 132   // bank = (4n + k) % 32, conflict-free
#define VSTR 136   // bank = (8k + n) % 32, conflict-free

__global__ __launch_bounds__(128, 2)
void attn_kernel(float* __restrict__ out) {
    const int qt = blockIdx.x;
    const int ch = blockIdx.y;
    const int nc = (qt >> 3) + 1;          // ceil(64(qt+1)/512)
    if (ch >= nc) return;

    __shared__ float Ks[BN][KSTR];
    __shared__ float Vs[BN][VSTR];
    __shared__ float Ps[4][16][36];

    const int tid  = threadIdx.x;
    const int warp = tid >> 5, lane = tid & 31;
    const int g    = lane >> 2, t4 = lane & 3;
    const int qm0  = qt * BM;
    const int row_base = qm0 + warp * 16;
    const float NEG_INF = __int_as_float(0xff800000u);
    const float SC = 0.02209708691207961f * 1.4426950408889634f;  // (1/sqrt(2048))*log2(e)

    const int kstart = ch * CHUNK;
    const int kend   = min(kstart + CHUNK, qm0 + BM);
    const int ntiles = (kend - kstart) / BN;

    // Q fragments: already tf32-rounded by proj -> raw bits
    uint32_t qf[16][4];
#pragma unroll
    for (int kt = 0; kt < 16; ++kt) {
        const float* qp = g_Q + (size_t)(row_base + g) * DH + kt * 8 + t4;
        qf[kt][0] = __float_as_uint(qp[0]);
        qf[kt][1] = __float_as_uint(qp[8 * DH]);
        qf[kt][2] = __float_as_uint(qp[4]);
        qf[kt][3] = __float_as_uint(qp[8 * DH + 4]);
    }

    float acc[16][4] = {};
    float m0r = NEG_INF, m1r = NEG_INF;
    float l0 = 0.f, l1 = 0.f;

    for (int j = 0; j < ntiles; ++j) {
        const int n0 = kstart + j * BN;

        // stage K/V tile (32 x 128)
#pragma unroll
        for (int t = 0; t < 8; ++t) {
            int i = tid + t * 128;
            int r = i >> 5, c4 = (i & 31) * 4;
            *(float4*)&Ks[r][c4] = *(const float4*)(g_K + (size_t)(n0 + r) * DH + c4);
            *(float4*)&Vs[r][c4] = *(const float4*)(g_V + (size_t)(n0 + r) * DH + c4);
        }
        __syncthreads();

        // S = Q . K^T  (16 x 32 per warp); K bits already tf32
        float s[4][4] = {};
#pragma unroll
        for (int kt = 0; kt < 16; ++kt) {
#pragma unroll
            for (int nt = 0; nt < 4; ++nt) {
                int n = nt * 8 + g;
                int c = kt * 8 + t4;
                uint32_t b0 = __float_as_uint(Ks[n][c]);
                uint32_t b1 = __float_as_uint(Ks[n][c + 4]);
                mma_tf32(s[nt], qf[kt], b0, b1);
            }
        }

        // exp2-domain scale + causal mask
        const int r0g = row_base + g, r1g = r0g + 8;
        const bool domask = (n0 + BN - 1 > row_base);
#pragma unroll
        for (int nt = 0; nt < 4; ++nt) {
            int c0 = n0 + nt * 8 + t4 * 2;
#pragma unroll
            for (int e = 0; e < 4; ++e) s[nt][e] *= SC;
            if (domask) {
                if (c0 > r0g)     s[nt][0] = NEG_INF;
                if (c0 + 1 > r0g) s[nt][1] = NEG_INF;
                if (c0 > r1g)     s[nt][2] = NEG_INF;
                if (c0 + 1 > r1g) s[nt][3] = NEG_INF;
            }
        }

        // online softmax (quad = 4 threads per row)
        float mx0 = fmaxf(fmaxf(s[0][0], s[0][1]), fmaxf(s[1][0], s[1][1]));
        mx0 = fmaxf(mx0, fmaxf(fmaxf(s[2][0], s[2][1]), fmaxf(s[3][0], s[3][1])));
        float mx1 = fmaxf(fmaxf(s[0][2], s[0][3]), fmaxf(s[1][2], s[1][3]));
        mx1 = fmaxf(mx1, fmaxf(fmaxf(s[2][2], s[2][3]), fmaxf(s[3][2], s[3][3])));
        mx0 = fmaxf(mx0, __shfl_xor_sync(0xffffffffu, mx0, 1));
        mx0 = fmaxf(mx0, __shfl_xor_sync(0xffffffffu, mx0, 2));
        mx1 = fmaxf(mx1, __shfl_xor_sync(0xffffffffu, mx1, 1));
        mx1 = fmaxf(mx1, __shfl_xor_sync(0xffffffffu, mx1, 2));

        float mn0 = fmaxf(m0r, mx0), mn1 = fmaxf(m1r, mx1);
        float mu0 = fmaxf(mn0, -1e30f), mu1 = fmaxf(mn1, -1e30f);
        float al0 = ex2(m0r - mu0), al1 = ex2(m1r - mu1);
        m0r = mn0; m1r = mn1;

        float rs0 = 0.f, rs1 = 0.f;
#pragma unroll
        for (int nt = 0; nt < 4; ++nt) {
            float p00 = ex2(s[nt][0] - mu0), p01 = ex2(s[nt][1] - mu0);
            float p10 = ex2(s[nt][2] - mu1), p11 = ex2(s[nt][3] - mu1);
            rs0 += p00 + p01; rs1 += p10 + p11;
            Ps[warp][g][nt * 8 + t4 * 2]         = __uint_as_float(f2tf(p00));
            Ps[warp][g][nt * 8 + t4 * 2 + 1]     = __uint_as_float(f2tf(p01));
            Ps[warp][g + 8][nt * 8 + t4 * 2]     = __uint_as_float(f2tf(p10));
            Ps[warp][g + 8][nt * 8 + t4 * 2 + 1] = __uint_as_float(f2tf(p11));
        }
        rs0 += __shfl_xor_sync(0xffffffffu, rs0, 1);
        rs0 += __shfl_xor_sync(0xffffffffu, rs0, 2);
        rs1 += __shfl_xor_sync(0xffffffffu, rs1, 1);
        rs1 += __shfl_xor_sync(0xffffffffu, rs1, 2);
        l0 = l0 * al0 + rs0;
        l1 = l1 * al1 + rs1;

#pragma unroll
        for (int nt = 0; nt < 16; ++nt) {
            acc[nt][0] *= al0; acc[nt][1] *= al0;
            acc[nt][2] *= al1; acc[nt][3] *= al1;
        }
        __syncwarp();

        // O += P . V
#pragma unroll
        for (int ks = 0; ks < 4; ++ks) {
            uint32_t a[4];
            a[0] = __float_as_uint(Ps[warp][g][ks * 8 + t4]);
            a[1] = __float_as_uint(Ps[warp][g + 8][ks * 8 + t4]);
            a[2] = __float_as_uint(Ps[warp][g][ks * 8 + t4 + 4]);
            a[3] = __float_as_uint(Ps[warp][g + 8][ks * 8 + t4 + 4]);
#pragma unroll
            for (int nt = 0; nt < 16; ++nt) {
                int vn = nt * 8 + g;
                int vk = ks * 8 + t4;
                uint32_t b0 = __float_as_uint(Vs[vk][vn]);
                uint32_t b1 = __float_as_uint(Vs[vk + 4][vn]);
                mma_tf32(acc[nt], a, b0, b1);
            }
        }
        __syncthreads();
    }

    if (nc == 1) {
        const float inv0 = 1.0f / l0, inv1 = 1.0f / l1;
#pragma unroll
        for (int nt = 0; nt < 16; ++nt) {
            int r = row_base + g;
            int c = nt * 8 + t4 * 2;
            out[(size_t)r * DH + c]           = acc[nt][0] * inv0;
            out[(size_t)r * DH + c + 1]       = acc[nt][1] * inv0;
            out[(size_t)(r + 8) * DH + c]     = acc[nt][2] * inv1;
            out[(size_t)(r + 8) * DH + c + 1] = acc[nt][3] * inv1;
        }
    } else {
        const int pslot = qt * MAXC + ch;
        float* Op = g_Opart + (size_t)pslot * 64 * DH;
        const int lr0 = warp * 16 + g, lr1 = lr0 + 8;
#pragma unroll
        for (int nt = 0; nt < 16; ++nt) {
            int c = nt * 8 + t4 * 2;
            Op[(size_t)lr0 * DH + c]     = acc[nt][0];
            Op[(size_t)lr0 * DH + c + 1] = acc[nt][1];
            Op[(size_t)lr1 * DH + c]     = acc[nt][2];
            Op[(size_t)lr1 * DH + c + 1] = acc[nt][3];
        }
        if (t4 == 0) {
            g_mpart[pslot * 64 + lr0] = m0r;
            g_lpart[pslot * 64 + lr0] = l0;
            g_mpart[pslot * 64 + lr1] = m1r;
            g_lpart[pslot * 64 + lr1] = l1;
        }
    }
}

// ---------------------------------------------------------------------------
// Combine partials for rows 512..4095 (q-tiles with >= 2 chunks).
// ---------------------------------------------------------------------------
__global__ __launch_bounds__(128)
void combine_kernel(float* __restrict__ out) {
    const int row = 512 + blockIdx.x;
    const int qt  = row >> 6;
    const int nc  = (qt >> 3) + 1;
    const int lr  = row & 63;
    const int col = threadIdx.x;

    float M = -1e30f;
    for (int c = 0; c < nc; ++c)
        M = fmaxf(M, g_mpart[(qt * MAXC + c) * 64 + lr]);

    float l = 0.f, o = 0.f;
    for (int c = 0; c < nc; ++c) {
        int pslot = qt * MAXC + c;
        float a = ex2(g_mpart[pslot * 64 + lr] - M);
        l += a * g_lpart[pslot * 64 + lr];
        o += a * g_Opart[((size_t)pslot * 64 + lr) * DH + col];
    }
    out[(size_t)row * DH + col] = o / l;
}

// ---------------------------------------------------------------------------

extern "C" void kernel_launch(void* const* d_in, const int* in_sizes, int n_in,
                              void* d_out, int out_size) {
    (void)in_sizes; (void)n_in; (void)out_size;
    const float* xq = (const float*)d_in[0];
    const float* xk = (const float*)d_in[1];
    const float* xv = (const float*)d_in[2];
    const float* wq = (const float*)d_in[3];
    const float* bq = (const float*)d_in[4];
    const float* wk = (const float*)d_in[5];
    const float* bk = (const float*)d_in[6];
    const float* wv = (const float*)d_in[7];
    const float* bv = (const float*)d_in[8];
    float* out = (float*)d_out;

    prep_w<<<1536, 256>>>(wq, wk, wv);
    proj_kernel<<<dim3(SEQ / 128, 3), 256>>>(xq, xk, xv, bq, bk, bv);
    attn_kernel<<<dim3(SEQ / BM, MAXC), 128>>>(out);
    combine_kernel<<<SEQ - 512, 128>>>(out);
}

// round 9
// speedup vs baseline: 1.2820x; 1.2678x over previous
#include <cuda_runtime.h>
#include <cstdint>
#include <cstddef>

#define SEQ     4096
#define DMODEL  2048
#define DH      128
#define CHUNK   512
#define MAXC    8

// Scratch (allocation-free rule: __device__ globals)
__device__ float g_Q[SEQ * DH];
__device__ float g_K[SEQ * DH];
__device__ float g_V[SEQ * DH];
// W pre-converted to tf32, fragment-pair order: [3][256 kb][128 n][4 t4][2]
__device__ float g_Wf[3 * 256 * 128 * 8];
// split-KV partials
__device__ float g_Opart[64 * MAXC * 64 * DH];
__device__ float g_mpart[64 * MAXC * 64];
__device__ float g_lpart[64 * MAXC * 64];

__device__ __forceinline__ uint32_t f2tf(float x) {
    uint32_t r;
    asm("cvt.rna.tf32.f32 %0, %1;" : "=r"(r) : "f"(x));
    return r;
}
__device__ __forceinline__ float ex2(float x) {
    float y;
    asm("ex2.approx.ftz.f32 %0, %1;" : "=f"(y) : "f"(x));
    return y;
}
__device__ __forceinline__ void mma_tf32(float d[4], const uint32_t a[4],
                                         uint32_t b0, uint32_t b1) {
    asm volatile(
        "mma.sync.aligned.m16n8k8.row.col.f32.tf32.tf32.f32 "
        "{%0,%1,%2,%3},{%4,%5,%6,%7},{%8,%9},{%0,%1,%2,%3};\n"
        : "+f"(d[0]), "+f"(d[1]), "+f"(d[2]), "+f"(d[3])
        : "r"(a[0]), "r"(a[1]), "r"(a[2]), "r"(a[3]), "r"(b0), "r"(b1));
}

// ---------------------------------------------------------------------------
// prep_w: round W to tf32 and reorder into MMA b-fragment pairs:
// g_Wf[mat][kb][n][t4][2] = { W[n][8kb+t4], W[n][8kb+t4+4] }
// ---------------------------------------------------------------------------
__global__ __launch_bounds__(256)
void prep_w(const float* __restrict__ wq, const float* __restrict__ wk,
            const float* __restrict__ wv) {
    int id = blockIdx.x * 256 + threadIdx.x;       // 0 .. 393215
    int mat = id >> 17;
    int rem = id & 131071;
    int kb = rem >> 9;
    int rem2 = rem & 511;
    int n = rem2 >> 2;
    int t4 = rem2 & 3;
    const float* W = (mat == 0) ? wq : (mat == 1) ? wk : wv;
    float a = W[(size_t)n * DMODEL + kb * 8 + t4];
    float b = W[(size_t)n * DMODEL + kb * 8 + t4 + 4];
    float2 o;
    o.x = __uint_as_float(f2tf(a));
    o.y = __uint_as_float(f2tf(b));
    *(float2*)&g_Wf[(((size_t)mat * 256 + kb) * 128 + n) * 8 + t4 * 2] = o;
}

// ---------------------------------------------------------------------------
// Projection (R3 proven structure: 64x128 tile, grid (64,3)=192 blocks, occ 2,
// register-prefetch single-buffer) with ONE change: b-operands come from
// pre-tf32 fragment-packed g_Wf -> one conflict-free LDS.64 per fragment,
// zero cvt in the b-path.
// ---------------------------------------------------------------------------
#define PSTR 36   // Xs: bank = (4g + t4) % 32, conflict-free

__global__ __launch_bounds__(256, 2)
void proj_kernel(const float* __restrict__ xq, const float* __restrict__ xk,
                 const float* __restrict__ xv,
                 const float* __restrict__ bq, const float* __restrict__ bk,
                 const float* __restrict__ bv) {
    __shared__ float Xs[64][PSTR];         // 9 KB
    __shared__ float Wf[4][128][8];        // 16 KB: [kb][n][t4*2 + half]

    const float* X; const float* bias; float* out; int mat;
    if (blockIdx.y == 0)      { X = xq; bias = bq; out = g_Q; mat = 0; }
    else if (blockIdx.y == 1) { X = xk; bias = bk; out = g_K; mat = 1; }
    else                      { X = xv; bias = bv; out = g_V; mat = 2; }

    const int tid  = threadIdx.x;
    const int warp = tid >> 5, lane = tid & 31;
    const int g    = lane >> 2, t4 = lane & 3;
    const int wm   = warp >> 1;   // 0..3 : 16 M-rows each
    const int wn   = warp & 1;    // 0..1 : 64 N-cols each
    const int m0   = blockIdx.x * 64;

    const float* gwf = g_Wf + (size_t)mat * 256 * 128 * 8;

    float acc[8][4] = {};

    float4 xr[2], wr[4];
    auto ld = [&](int k0) {
        // X: 64 rows x 32 floats = 512 float4 -> 2 per thread
#pragma unroll
        for (int t = 0; t < 2; ++t) {
            int i = tid + t * 256;
            int r = i >> 3, c4 = (i & 7) * 4;
            xr[t] = *(const float4*)(X + (size_t)(m0 + r) * DMODEL + k0 + c4);
        }
        // W fragments kb = k0/8 .. +3 : 4*128*8 floats = 1024 float4 -> 4/thread
#pragma unroll
        for (int t = 0; t < 4; ++t) {
            int i = tid + t * 256;
            int kb = i >> 8;
            int rem = i & 255;
            int n = rem >> 1, half = rem & 1;
            wr[t] = *(const float4*)(gwf + (((size_t)(k0 >> 3) + kb) * 128 + n) * 8 + half * 4);
        }
    };
    auto st = [&]() {
#pragma unroll
        for (int t = 0; t < 2; ++t) {
            int i = tid + t * 256;
            int r = i >> 3, c4 = (i & 7) * 4;
            *(float4*)&Xs[r][c4] = xr[t];
        }
#pragma unroll
        for (int t = 0; t < 4; ++t) {
            int i = tid + t * 256;
            int kb = i >> 8;
            int rem = i & 255;
            int n = rem >> 1, half = rem & 1;
            *(float4*)&Wf[kb][n][half * 4] = wr[t];
        }
    };

    ld(0); st();
    __syncthreads();

    for (int k0 = 0; k0 < DMODEL; k0 += 32) {
        bool more = (k0 + 32 < DMODEL);
        if (more) ld(k0 + 32);   // overlap global fetch with MMA

#pragma unroll
        for (int kk = 0; kk < 4; ++kk) {     // K-step 8 within the stage
            uint32_t a[4];
            {
                int r = wm * 16 + g;
                int c = kk * 8 + t4;
                a[0] = f2tf(Xs[r][c]);
                a[1] = f2tf(Xs[r + 8][c]);
                a[2] = f2tf(Xs[r][c + 4]);
                a[3] = f2tf(Xs[r + 8][c + 4]);
            }
#pragma unroll
            for (int nt = 0; nt < 8; ++nt) {
                int n = wn * 64 + nt * 8 + g;
                float2 w2 = *(float2*)&Wf[kk][n][t4 * 2];   // LDS.64, conflict-free
                mma_tf32(acc[nt], a, __float_as_uint(w2.x), __float_as_uint(w2.y));
            }
        }
        __syncthreads();
        if (more) { st(); __syncthreads(); }
    }

#pragma unroll
    for (int nt = 0; nt < 8; ++nt) {
        int r = m0 + wm * 16 + g;
        int c = wn * 64 + nt * 8 + t4 * 2;
        float b0 = bias[c], b1 = bias[c + 1];
        out[(size_t)r * DH + c]           = __uint_as_float(f2tf(acc[nt][0] + b0));
        out[(size_t)r * DH + c + 1]       = __uint_as_float(f2tf(acc[nt][1] + b1));
        out[(size_t)(r + 8) * DH + c]     = __uint_as_float(f2tf(acc[nt][2] + b0));
        out[(size_t)(r + 8) * DH + c + 1] = __uint_as_float(f2tf(acc[nt][3] + b1));
    }
}

// ---------------------------------------------------------------------------
// Split-KV causal flash attention (exact R3 version from the 145.4 run).
// grid = (64 q-tiles, 8 chunks), 128 thr.
// ---------------------------------------------------------------------------
#define BM 64
#define BN 32
#define KSTR 132   // bank = (4n + k) % 32, conflict-free
#define VSTR 136   // bank = (8k + n) % 32, conflict-free

__global__ __launch_bounds__(128, 2)
void attn_kernel(float* __restrict__ out) {
    const int qt = blockIdx.x;
    const int ch = blockIdx.y;
    const int nc = (qt >> 3) + 1;          // ceil(64(qt+1)/512)
    if (ch >= nc) return;

    __shared__ float Ks[BN][KSTR];
    __shared__ float Vs[BN][VSTR];
    __shared__ float Ps[4][16][36];

    const int tid  = threadIdx.x;
    const int warp = tid >> 5, lane = tid & 31;
    const int g    = lane >> 2, t4 = lane & 3;
    const int qm0  = qt * BM;
    const int row_base = qm0 + warp * 16;
    const float NEG_INF = __int_as_float(0xff800000u);
    const float SC = 0.02209708691207961f * 1.4426950408889634f;  // (1/sqrt(2048))*log2(e)

    const int kstart = ch * CHUNK;
    const int kend   = min(kstart + CHUNK, qm0 + BM);
    const int ntiles = (kend - kstart) / BN;

    // Q fragments: already tf32-rounded by proj -> raw bits
    uint32_t qf[16][4];
#pragma unroll
    for (int kt = 0; kt < 16; ++kt) {
        const float* qp = g_Q + (size_t)(row_base + g) * DH + kt * 8 + t4;
        qf[kt][0] = __float_as_uint(qp[0]);
        qf[kt][1] = __float_as_uint(qp[8 * DH]);
        qf[kt][2] = __float_as_uint(qp[4]);
        qf[kt][3] = __float_as_uint(qp[8 * DH + 4]);
    }

    float acc[16][4] = {};
    float m0r = NEG_INF, m1r = NEG_INF;
    float l0 = 0.f, l1 = 0.f;

    for (int j = 0; j < ntiles; ++j) {
        const int n0 = kstart + j * BN;

        // stage K/V tile (32 x 128)
#pragma unroll
        for (int t = 0; t < 8; ++t) {
            int i = tid + t * 128;
            int r = i >> 5, c4 = (i & 31) * 4;
            *(float4*)&Ks[r][c4] = *(const float4*)(g_K + (size_t)(n0 + r) * DH + c4);
            *(float4*)&Vs[r][c4] = *(const float4*)(g_V + (size_t)(n0 + r) * DH + c4);
        }
        __syncthreads();

        // S = Q . K^T  (16 x 32 per warp); K bits already tf32
        float s[4][4] = {};
#pragma unroll
        for (int kt = 0; kt < 16; ++kt) {
#pragma unroll
            for (int nt = 0; nt < 4; ++nt) {
                int n = nt * 8 + g;
                int c = kt * 8 + t4;
                uint32_t b0 = __float_as_uint(Ks[n][c]);
                uint32_t b1 = __float_as_uint(Ks[n][c + 4]);
                mma_tf32(s[nt], qf[kt], b0, b1);
            }
        }

        // exp2-domain scale + causal mask
        const int r0g = row_base + g, r1g = r0g + 8;
        const bool domask = (n0 + BN - 1 > row_base);
#pragma unroll
        for (int nt = 0; nt < 4; ++nt) {
            int c0 = n0 + nt * 8 + t4 * 2;
#pragma unroll
            for (int e = 0; e < 4; ++e) s[nt][e] *= SC;
            if (domask) {
                if (c0 > r0g)     s[nt][0] = NEG_INF;
                if (c0 + 1 > r0g) s[nt][1] = NEG_INF;
                if (c0 > r1g)     s[nt][2] = NEG_INF;
                if (c0 + 1 > r1g) s[nt][3] = NEG_INF;
            }
        }

        // online softmax (quad = 4 threads per row)
        float mx0 = fmaxf(fmaxf(s[0][0], s[0][1]), fmaxf(s[1][0], s[1][1]));
        mx0 = fmaxf(mx0, fmaxf(fmaxf(s[2][0], s[2][1]), fmaxf(s[3][0], s[3][1])));
        float mx1 = fmaxf(fmaxf(s[0][2], s[0][3]), fmaxf(s[1][2], s[1][3]));
        mx1 = fmaxf(mx1, fmaxf(fmaxf(s[2][2], s[2][3]), fmaxf(s[3][2], s[3][3])));
        mx0 = fmaxf(mx0, __shfl_xor_sync(0xffffffffu, mx0, 1));
        mx0 = fmaxf(mx0, __shfl_xor_sync(0xffffffffu, mx0, 2));
        mx1 = fmaxf(mx1, __shfl_xor_sync(0xffffffffu, mx1, 1));
        mx1 = fmaxf(mx1, __shfl_xor_sync(0xffffffffu, mx1, 2));

        float mn0 = fmaxf(m0r, mx0), mn1 = fmaxf(m1r, mx1);
        float mu0 = fmaxf(mn0, -1e30f), mu1 = fmaxf(mn1, -1e30f);
        float al0 = ex2(m0r - mu0), al1 = ex2(m1r - mu1);
        m0r = mn0; m1r = mn1;

        float rs0 = 0.f, rs1 = 0.f;
#pragma unroll
        for (int nt = 0; nt < 4; ++nt) {
            float p00 = ex2(s[nt][0] - mu0), p01 = ex2(s[nt][1] - mu0);
            float p10 = ex2(s[nt][2] - mu1), p11 = ex2(s[nt][3] - mu1);
            rs0 += p00 + p01; rs1 += p10 + p11;
            Ps[warp][g][nt * 8 + t4 * 2]         = __uint_as_float(f2tf(p00));
            Ps[warp][g][nt * 8 + t4 * 2 + 1]     = __uint_as_float(f2tf(p01));
            Ps[warp][g + 8][nt * 8 + t4 * 2]     = __uint_as_float(f2tf(p10));
            Ps[warp][g + 8][nt * 8 + t4 * 2 + 1] = __uint_as_float(f2tf(p11));
        }
        rs0 += __shfl_xor_sync(0xffffffffu, rs0, 1);
        rs0 += __shfl_xor_sync(0xffffffffu, rs0, 2);
        rs1 += __shfl_xor_sync(0xffffffffu, rs1, 1);
        rs1 += __shfl_xor_sync(0xffffffffu, rs1, 2);
        l0 = l0 * al0 + rs0;
        l1 = l1 * al1 + rs1;

#pragma unroll
        for (int nt = 0; nt < 16; ++nt) {
            acc[nt][0] *= al0; acc[nt][1] *= al0;
            acc[nt][2] *= al1; acc[nt][3] *= al1;
        }
        __syncwarp();

        // O += P . V
#pragma unroll
        for (int ks = 0; ks < 4; ++ks) {
            uint32_t a[4];
            a[0] = __float_as_uint(Ps[warp][g][ks * 8 + t4]);
            a[1] = __float_as_uint(Ps[warp][g + 8][ks * 8 + t4]);
            a[2] = __float_as_uint(Ps[warp][g][ks * 8 + t4 + 4]);
            a[3] = __float_as_uint(Ps[warp][g + 8][ks * 8 + t4 + 4]);
#pragma unroll
            for (int nt = 0; nt < 16; ++nt) {
                int vn = nt * 8 + g;
                int vk = ks * 8 + t4;
                uint32_t b0 = __float_as_uint(Vs[vk][vn]);
                uint32_t b1 = __float_as_uint(Vs[vk + 4][vn]);
                mma_tf32(acc[nt], a, b0, b1);
            }
        }
        __syncthreads();
    }

    if (nc == 1) {
        const float inv0 = 1.0f / l0, inv1 = 1.0f / l1;
#pragma unroll
        for (int nt = 0; nt < 16; ++nt) {
            int r = row_base + g;
            int c = nt * 8 + t4 * 2;
            out[(size_t)r * DH + c]           = acc[nt][0] * inv0;
            out[(size_t)r * DH + c + 1]       = acc[nt][1] * inv0;
            out[(size_t)(r + 8) * DH + c]     = acc[nt][2] * inv1;
            out[(size_t)(r + 8) * DH + c + 1] = acc[nt][3] * inv1;
        }
    } else {
        const int pslot = qt * MAXC + ch;
        float* Op = g_Opart + (size_t)pslot * 64 * DH;
        const int lr0 = warp * 16 + g, lr1 = lr0 + 8;
#pragma unroll
        for (int nt = 0; nt < 16; ++nt) {
            int c = nt * 8 + t4 * 2;
            Op[(size_t)lr0 * DH + c]     = acc[nt][0];
            Op[(size_t)lr0 * DH + c + 1] = acc[nt][1];
            Op[(size_t)lr1 * DH + c]     = acc[nt][2];
            Op[(size_t)lr1 * DH + c + 1] = acc[nt][3];
        }
        if (t4 == 0) {
            g_mpart[pslot * 64 + lr0] = m0r;
            g_lpart[pslot * 64 + lr0] = l0;
            g_mpart[pslot * 64 + lr1] = m1r;
            g_lpart[pslot * 64 + lr1] = l1;
        }
    }
}

// ---------------------------------------------------------------------------
// Combine partials for rows 512..4095 (q-tiles with >= 2 chunks).
// ---------------------------------------------------------------------------
__global__ __launch_bounds__(128)
void combine_kernel(float* __restrict__ out) {
    const int row = 512 + blockIdx.x;
    const int qt  = row >> 6;
    const int nc  = (qt >> 3) + 1;
    const int lr  = row & 63;
    const int col = threadIdx.x;

    float M = -1e30f;
    for (int c = 0; c < nc; ++c)
        M = fmaxf(M, g_mpart[(qt * MAXC + c) * 64 + lr]);

    float l = 0.f, o = 0.f;
    for (int c = 0; c < nc; ++c) {
        int pslot = qt * MAXC + c;
        float a = ex2(g_mpart[pslot * 64 + lr] - M);
        l += a * g_lpart[pslot * 64 + lr];
        o += a * g_Opart[((size_t)pslot * 64 + lr) * DH + col];
    }
    out[(size_t)row * DH + col] = o / l;
}

// ---------------------------------------------------------------------------

extern "C" void kernel_launch(void* const* d_in, const int* in_sizes, int n_in,
                              void* d_out, int out_size) {
    (void)in_sizes; (void)n_in; (void)out_size;
    const float* xq = (const float*)d_in[0];
    const float* xk = (const float*)d_in[1];
    const float* xv = (const float*)d_in[2];
    const float* wq = (const float*)d_in[3];
    const float* bq = (const float*)d_in[4];
    const float* wk = (const float*)d_in[5];
    const float* bk = (const float*)d_in[6];
    const float* wv = (const float*)d_in[7];
    const float* bv = (const float*)d_in[8];
    float* out = (float*)d_out;

    prep_w<<<1536, 256>>>(wq, wk, wv);
    proj_kernel<<<dim3(SEQ / 64, 3), 256>>>(xq, xk, xv, bq, bk, bv);
    attn_kernel<<<dim3(SEQ / BM, MAXC), 128>>>(out);
    combine_kernel<<<SEQ - 512, 128>>>(out);
}

// round 10
// speedup vs baseline: 1.4004x; 1.0923x over previous
#include <cuda_runtime.h>
#include <cstdint>
#include <cstddef>

#define SEQ     4096
#define DMODEL  2048
#define DH      128
#define CHUNK   512
#define MAXC    8

// Scratch (allocation-free rule: __device__ globals)
__device__ float g_Q[SEQ * DH];
__device__ float g_K[SEQ * DH];
__device__ float g_V[SEQ * DH];
// W pre-converted to tf32, fragment-pair order: [3][256 kb][128 n][4 t4][2]
__device__ float g_Wf[3 * 256 * 128 * 8];
// split-KV partials
__device__ float g_Opart[64 * MAXC * 64 * DH];
__device__ float g_mpart[64 * MAXC * 64];
__device__ float g_lpart[64 * MAXC * 64];

__device__ __forceinline__ uint32_t f2tf(float x) {
    uint32_t r;
    asm("cvt.rna.tf32.f32 %0, %1;" : "=r"(r) : "f"(x));
    return r;
}
__device__ __forceinline__ float ex2(float x) {
    float y;
    asm("ex2.approx.ftz.f32 %0, %1;" : "=f"(y) : "f"(x));
    return y;
}
__device__ __forceinline__ void mma_tf32(float d[4], const uint32_t a[4],
                                         uint32_t b0, uint32_t b1) {
    asm volatile(
        "mma.sync.aligned.m16n8k8.row.col.f32.tf32.tf32.f32 "
        "{%0,%1,%2,%3},{%4,%5,%6,%7},{%8,%9},{%0,%1,%2,%3};\n"
        : "+f"(d[0]), "+f"(d[1]), "+f"(d[2]), "+f"(d[3])
        : "r"(a[0]), "r"(a[1]), "r"(a[2]), "r"(a[3]), "r"(b0), "r"(b1));
}
__device__ __forceinline__ void cpa16(uint32_t dst, const void* src) {
    asm volatile("cp.async.cg.shared.global [%0], [%1], 16;\n" :: "r"(dst), "l"(src));
}
__device__ __forceinline__ void cp_commit() {
    asm volatile("cp.async.commit_group;\n" ::);
}
template <int N>
__device__ __forceinline__ void cp_wait() {
    asm volatile("cp.async.wait_group %0;\n" :: "n"(N));
}
__device__ __forceinline__ uint32_t s2u(const void* p) {
    return (uint32_t)__cvta_generic_to_shared(p);
}

// ---------------------------------------------------------------------------
// prep_w: round W to tf32 and reorder into MMA b-fragment pairs:
// g_Wf[mat][kb][n][t4][2] = { W[n][8kb+t4], W[n][8kb+t4+4] }
// ---------------------------------------------------------------------------
__global__ __launch_bounds__(256)
void prep_w(const float* __restrict__ wq, const float* __restrict__ wk,
            const float* __restrict__ wv) {
    int id = blockIdx.x * 256 + threadIdx.x;       // 0 .. 393215
    int mat = id >> 17;
    int rem = id & 131071;
    int kb = rem >> 9;
    int rem2 = rem & 511;
    int n = rem2 >> 2;
    int t4 = rem2 & 3;
    const float* W = (mat == 0) ? wq : (mat == 1) ? wk : wv;
    float a = W[(size_t)n * DMODEL + kb * 8 + t4];
    float b = W[(size_t)n * DMODEL + kb * 8 + t4 + 4];
    float2 o;
    o.x = __uint_as_float(f2tf(a));
    o.y = __uint_as_float(f2tf(b));
    *(float2*)&g_Wf[(((size_t)mat * 256 + kb) * 128 + n) * 8 + t4 * 2] = o;
}

// ---------------------------------------------------------------------------
// Projection v4: same 64x128 tile / grid(64,3) / 256 thr / MMA + smem layouts
// as the proven R9 kernel, but staging is a 3-stage cp.async pipeline:
//   Xs[3][64][36] raw fp32 (cvt at use), Wf[3][4][128][8] pre-tf32 pairs.
// wait_group<1> + one __syncthreads per iteration -> ~2 compute phases of
// DRAM latency cover, 12 outstanding 16B loads per thread.
// ---------------------------------------------------------------------------
#define PJ_DEPTH 3
#define XSTR     36   // bank = (4g + t4) % 32, conflict-free (36%32 = 4)
#define XS_FL    (64 * XSTR)          // floats per X stage
#define WF_FL    (4 * 128 * 8)        // floats per W stage
#define PJ_SMEM  (PJ_DEPTH * (XS_FL + WF_FL) * 4)   // 76800 B

__global__ __launch_bounds__(256, 2)
void proj_kernel(const float* __restrict__ xq, const float* __restrict__ xk,
                 const float* __restrict__ xv,
                 const float* __restrict__ bq, const float* __restrict__ bk,
                 const float* __restrict__ bv) {
    extern __shared__ float sm[];
    float* Xs  = sm;                          // [3][64][36]
    float* WfS = sm + PJ_DEPTH * XS_FL;       // [3][4][128][8]

    const float* X; const float* bias; float* out; int mat;
    if (blockIdx.y == 0)      { X = xq; bias = bq; out = g_Q; mat = 0; }
    else if (blockIdx.y == 1) { X = xk; bias = bk; out = g_K; mat = 1; }
    else                      { X = xv; bias = bv; out = g_V; mat = 2; }

    const int tid  = threadIdx.x;
    const int warp = tid >> 5, lane = tid & 31;
    const int g    = lane >> 2, t4 = lane & 3;
    const int wm   = warp >> 1;   // 0..3 : 16 M-rows each
    const int wn   = warp & 1;    // 0..1 : 64 N-cols each
    const int m0   = blockIdx.x * 64;

    const float* gwf = g_Wf + (size_t)mat * 256 * 128 * 8;

    float acc[8][4] = {};

    // stage sidx covers K [32*sidx, 32*sidx+32), written to slot sidx % 3
    auto issue = [&](int sidx) {
        const int s  = sidx % PJ_DEPTH;
        const int k0 = sidx * 32;
        // X: 64 rows x 32 floats = 512 16B chunks -> 2 per thread
#pragma unroll
        for (int t = 0; t < 2; ++t) {
            int i = tid + t * 256;
            int r = i >> 3, c4 = (i & 7) * 4;
            cpa16(s2u(&Xs[(s * 64 + r) * XSTR + c4]),
                  X + (size_t)(m0 + r) * DMODEL + k0 + c4);
        }
        // W frags kb = k0/8 .. +3 : 1024 16B chunks -> 4 per thread
#pragma unroll
        for (int t = 0; t < 4; ++t) {
            int i = tid + t * 256;
            int kb = i >> 8;
            int rem = i & 255;
            int n = rem >> 1, half = rem & 1;
            cpa16(s2u(&WfS[((s * 4 + kb) * 128 + n) * 8 + half * 4]),
                  gwf + (((size_t)(k0 >> 3) + kb) * 128 + n) * 8 + half * 4);
        }
        cp_commit();
    };

    issue(0); issue(1);

    const int NK = DMODEL / 32;   // 64 stages
    for (int i = 0; i < NK; ++i) {
        if (i + 2 < NK) { cp_wait<1>(); } else { cp_wait<0>(); }
        __syncthreads();                 // stage i visible; slot (i+2)%3 free
        if (i + 2 < NK) issue(i + 2);

        const int s = i % PJ_DEPTH;
        const float* Xc = &Xs[s * XS_FL];
        const float* Wc = &WfS[s * WF_FL];

#pragma unroll
        for (int kk = 0; kk < 4; ++kk) {     // K-step 8 within the stage
            uint32_t a[4];
            {
                int r = wm * 16 + g;
                int c = kk * 8 + t4;
                a[0] = f2tf(Xc[r * XSTR + c]);
                a[1] = f2tf(Xc[(r + 8) * XSTR + c]);
                a[2] = f2tf(Xc[r * XSTR + c + 4]);
                a[3] = f2tf(Xc[(r + 8) * XSTR + c + 4]);
            }
#pragma unroll
            for (int nt = 0; nt < 8; ++nt) {
                int n = wn * 64 + nt * 8 + g;
                float2 w2 = *(const float2*)&Wc[(kk * 128 + n) * 8 + t4 * 2];
                mma_tf32(acc[nt], a, __float_as_uint(w2.x), __float_as_uint(w2.y));
            }
        }
    }

#pragma unroll
    for (int nt = 0; nt < 8; ++nt) {
        int r = m0 + wm * 16 + g;
        int c = wn * 64 + nt * 8 + t4 * 2;
        float b0 = bias[c], b1 = bias[c + 1];
        out[(size_t)r * DH + c]           = __uint_as_float(f2tf(acc[nt][0] + b0));
        out[(size_t)r * DH + c + 1]       = __uint_as_float(f2tf(acc[nt][1] + b1));
        out[(size_t)(r + 8) * DH + c]     = __uint_as_float(f2tf(acc[nt][2] + b0));
        out[(size_t)(r + 8) * DH + c + 1] = __uint_as_float(f2tf(acc[nt][3] + b1));
    }
}

// ---------------------------------------------------------------------------
// Split-KV causal flash attention (exact R9 version from the 139.3 run).
// grid = (64 q-tiles, 8 chunks), 128 thr.
// ---------------------------------------------------------------------------
#define BM 64
#define BN 32
#define KSTR 132   // bank = (4n + k) % 32, conflict-free
#define VSTR 136   // bank = (8k + n) % 32, conflict-free

__global__ __launch_bounds__(128, 2)
void attn_kernel(float* __restrict__ out) {
    const int qt = blockIdx.x;
    const int ch = blockIdx.y;
    const int nc = (qt >> 3) + 1;          // ceil(64(qt+1)/512)
    if (ch >= nc) return;

    __shared__ float Ks[BN][KSTR];
    __shared__ float Vs[BN][VSTR];
    __shared__ float Ps[4][16][36];

    const int tid  = threadIdx.x;
    const int warp = tid >> 5, lane = tid & 31;
    const int g    = lane >> 2, t4 = lane & 3;
    const int qm0  = qt * BM;
    const int row_base = qm0 + warp * 16;
    const float NEG_INF = __int_as_float(0xff800000u);
    const float SC = 0.02209708691207961f * 1.4426950408889634f;  // (1/sqrt(2048))*log2(e)

    const int kstart = ch * CHUNK;
    const int kend   = min(kstart + CHUNK, qm0 + BM);
    const int ntiles = (kend - kstart) / BN;

    // Q fragments: already tf32-rounded by proj -> raw bits
    uint32_t qf[16][4];
#pragma unroll
    for (int kt = 0; kt < 16; ++kt) {
        const float* qp = g_Q + (size_t)(row_base + g) * DH + kt * 8 + t4;
        qf[kt][0] = __float_as_uint(qp[0]);
        qf[kt][1] = __float_as_uint(qp[8 * DH]);
        qf[kt][2] = __float_as_uint(qp[4]);
        qf[kt][3] = __float_as_uint(qp[8 * DH + 4]);
    }

    float acc[16][4] = {};
    float m0r = NEG_INF, m1r = NEG_INF;
    float l0 = 0.f, l1 = 0.f;

    for (int j = 0; j < ntiles; ++j) {
        const int n0 = kstart + j * BN;

        // stage K/V tile (32 x 128)
#pragma unroll
        for (int t = 0; t < 8; ++t) {
            int i = tid + t * 128;
            int r = i >> 5, c4 = (i & 31) * 4;
            *(float4*)&Ks[r][c4] = *(const float4*)(g_K + (size_t)(n0 + r) * DH + c4);
            *(float4*)&Vs[r][c4] = *(const float4*)(g_V + (size_t)(n0 + r) * DH + c4);
        }
        __syncthreads();

        // S = Q . K^T  (16 x 32 per warp); K bits already tf32
        float s[4][4] = {};
#pragma unroll
        for (int kt = 0; kt < 16; ++kt) {
#pragma unroll
            for (int nt = 0; nt < 4; ++nt) {
                int n = nt * 8 + g;
                int c = kt * 8 + t4;
                uint32_t b0 = __float_as_uint(Ks[n][c]);
                uint32_t b1 = __float_as_uint(Ks[n][c + 4]);
                mma_tf32(s[nt], qf[kt], b0, b1);
            }
        }

        // exp2-domain scale + causal mask
        const int r0g = row_base + g, r1g = r0g + 8;
        const bool domask = (n0 + BN - 1 > row_base);
#pragma unroll
        for (int nt = 0; nt < 4; ++nt) {
            int c0 = n0 + nt * 8 + t4 * 2;
#pragma unroll
            for (int e = 0; e < 4; ++e) s[nt][e] *= SC;
            if (domask) {
                if (c0 > r0g)     s[nt][0] = NEG_INF;
                if (c0 + 1 > r0g) s[nt][1] = NEG_INF;
                if (c0 > r1g)     s[nt][2] = NEG_INF;
                if (c0 + 1 > r1g) s[nt][3] = NEG_INF;
            }
        }

        // online softmax (quad = 4 threads per row)
        float mx0 = fmaxf(fmaxf(s[0][0], s[0][1]), fmaxf(s[1][0], s[1][1]));
        mx0 = fmaxf(mx0, fmaxf(fmaxf(s[2][0], s[2][1]), fmaxf(s[3][0], s[3][1])));
        float mx1 = fmaxf(fmaxf(s[0][2], s[0][3]), fmaxf(s[1][2], s[1][3]));
        mx1 = fmaxf(mx1, fmaxf(fmaxf(s[2][2], s[2][3]), fmaxf(s[3][2], s[3][3])));
        mx0 = fmaxf(mx0, __shfl_xor_sync(0xffffffffu, mx0, 1));
        mx0 = fmaxf(mx0, __shfl_xor_sync(0xffffffffu, mx0, 2));
        mx1 = fmaxf(mx1, __shfl_xor_sync(0xffffffffu, mx1, 1));
        mx1 = fmaxf(mx1, __shfl_xor_sync(0xffffffffu, mx1, 2));

        float mn0 = fmaxf(m0r, mx0), mn1 = fmaxf(m1r, mx1);
        float mu0 = fmaxf(mn0, -1e30f), mu1 = fmaxf(mn1, -1e30f);
        float al0 = ex2(m0r - mu0), al1 = ex2(m1r - mu1);
        m0r = mn0; m1r = mn1;

        float rs0 = 0.f, rs1 = 0.f;
#pragma unroll
        for (int nt = 0; nt < 4; ++nt) {
            float p00 = ex2(s[nt][0] - mu0), p01 = ex2(s[nt][1] - mu0);
            float p10 = ex2(s[nt][2] - mu1), p11 = ex2(s[nt][3] - mu1);
            rs0 += p00 + p01; rs1 += p10 + p11;
            Ps[warp][g][nt * 8 + t4 * 2]         = __uint_as_float(f2tf(p00));
            Ps[warp][g][nt * 8 + t4 * 2 + 1]     = __uint_as_float(f2tf(p01));
            Ps[warp][g + 8][nt * 8 + t4 * 2]     = __uint_as_float(f2tf(p10));
            Ps[warp][g + 8][nt * 8 + t4 * 2 + 1] = __uint_as_float(f2tf(p11));
        }
        rs0 += __shfl_xor_sync(0xffffffffu, rs0, 1);
        rs0 += __shfl_xor_sync(0xffffffffu, rs0, 2);
        rs1 += __shfl_xor_sync(0xffffffffu, rs1, 1);
        rs1 += __shfl_xor_sync(0xffffffffu, rs1, 2);
        l0 = l0 * al0 + rs0;
        l1 = l1 * al1 + rs1;

#pragma unroll
        for (int nt = 0; nt < 16; ++nt) {
            acc[nt][0] *= al0; acc[nt][1] *= al0;
            acc[nt][2] *= al1; acc[nt][3] *= al1;
        }
        __syncwarp();

        // O += P . V
#pragma unroll
        for (int ks = 0; ks < 4; ++ks) {
            uint32_t a[4];
            a[0] = __float_as_uint(Ps[warp][g][ks * 8 + t4]);
            a[1] = __float_as_uint(Ps[warp][g + 8][ks * 8 + t4]);
            a[2] = __float_as_uint(Ps[warp][g][ks * 8 + t4 + 4]);
            a[3] = __float_as_uint(Ps[warp][g + 8][ks * 8 + t4 + 4]);
#pragma unroll
            for (int nt = 0; nt < 16; ++nt) {
                int vn = nt * 8 + g;
                int vk = ks * 8 + t4;
                uint32_t b0 = __float_as_uint(Vs[vk][vn]);
                uint32_t b1 = __float_as_uint(Vs[vk + 4][vn]);
                mma_tf32(acc[nt], a, b0, b1);
            }
        }
        __syncthreads();
    }

    if (nc == 1) {
        const float inv0 = 1.0f / l0, inv1 = 1.0f / l1;
#pragma unroll
        for (int nt = 0; nt < 16; ++nt) {
            int r = row_base + g;
            int c = nt * 8 + t4 * 2;
            out[(size_t)r * DH + c]           = acc[nt][0] * inv0;
            out[(size_t)r * DH + c + 1]       = acc[nt][1] * inv0;
            out[(size_t)(r + 8) * DH + c]     = acc[nt][2] * inv1;
            out[(size_t)(r + 8) * DH + c + 1] = acc[nt][3] * inv1;
        }
    } else {
        const int pslot = qt * MAXC + ch;
        float* Op = g_Opart + (size_t)pslot * 64 * DH;
        const int lr0 = warp * 16 + g, lr1 = lr0 + 8;
#pragma unroll
        for (int nt = 0; nt < 16; ++nt) {
            int c = nt * 8 + t4 * 2;
            Op[(size_t)lr0 * DH + c]     = acc[nt][0];
            Op[(size_t)lr0 * DH + c + 1] = acc[nt][1];
            Op[(size_t)lr1 * DH + c]     = acc[nt][2];
            Op[(size_t)lr1 * DH + c + 1] = acc[nt][3];
        }
        if (t4 == 0) {
            g_mpart[pslot * 64 + lr0] = m0r;
            g_lpart[pslot * 64 + lr0] = l0;
            g_mpart[pslot * 64 + lr1] = m1r;
            g_lpart[pslot * 64 + lr1] = l1;
        }
    }
}

// ---------------------------------------------------------------------------
// Combine partials for rows 512..4095 (q-tiles with >= 2 chunks).
// ---------------------------------------------------------------------------
__global__ __launch_bounds__(128)
void combine_kernel(float* __restrict__ out) {
    const int row = 512 + blockIdx.x;
    const int qt  = row >> 6;
    const int nc  = (qt >> 3) + 1;
    const int lr  = row & 63;
    const int col = threadIdx.x;

    float M = -1e30f;
    for (int c = 0; c < nc; ++c)
        M = fmaxf(M, g_mpart[(qt * MAXC + c) * 64 + lr]);

    float l = 0.f, o = 0.f;
    for (int c = 0; c < nc; ++c) {
        int pslot = qt * MAXC + c;
        float a = ex2(g_mpart[pslot * 64 + lr] - M);
        l += a * g_lpart[pslot * 64 + lr];
        o += a * g_Opart[((size_t)pslot * 64 + lr) * DH + col];
    }
    out[(size_t)row * DH + col] = o / l;
}

// ---------------------------------------------------------------------------

extern "C" void kernel_launch(void* const* d_in, const int* in_sizes, int n_in,
                              void* d_out, int out_size) {
    (void)in_sizes; (void)n_in; (void)out_size;
    const float* xq = (const float*)d_in[0];
    const float* xk = (const float*)d_in[1];
    const float* xv = (const float*)d_in[2];
    const float* wq = (const float*)d_in[3];
    const float* bq = (const float*)d_in[4];
    const float* wk = (const float*)d_in[5];
    const float* bk = (const float*)d_in[6];
    const float* wv = (const float*)d_in[7];
    const float* bv = (const float*)d_in[8];
    float* out = (float*)d_out;

    cudaFuncSetAttribute(proj_kernel, cudaFuncAttributeMaxDynamicSharedMemorySize, PJ_SMEM);

    prep_w<<<1536, 256>>>(wq, wk, wv);
    proj_kernel<<<dim3(SEQ / 64, 3), 256, PJ_SMEM>>>(xq, xk, xv, bq, bk, bv);
    attn_kernel<<<dim3(SEQ / BM, MAXC), 128>>>(out);
    combine_kernel<<<SEQ - 512, 128>>>(out);
}